// round 5
// baseline (speedup 1.0000x reference)
#include <cuda_runtime.h>
#include <math.h>

// ---------------------------------------------------------------------------
// FSC loss, round 5: packed f32x2 complex butterflies (re,im in one 64-bit
// reg), warp-per-line 128-pt shuffle FFT, single in-place 134 MB scratch,
// Hermitian pair-halved reduction with fused loss + self-resetting state.
// Layout after kernel B: plane index pz holds frequency fz = rev7(pz);
// within a plane, natural (fx, fy).
// ---------------------------------------------------------------------------

typedef unsigned long long u64;

#define PAD 129
#define SMEM_FFT (128 * PAD * 8)     // 132096 B (one u64 plane, padded)
#define PIF 3.14159265358979323846f

static __device__ u64    g_fft[8u * 128u * 128u * 128u];   // 134 MB scratch
static __device__ double g_acc[8][65][3];                  // num, d1, d2
static __device__ unsigned int g_ctr = 0;

__device__ __forceinline__ int rev7(int i) { return (int)(__brev((unsigned)i) >> 25); }

// ---- packed f32x2 helpers (value = (re, im) in lo/hi 32 bits) -------------
__device__ __forceinline__ u64 pk2(float lo, float hi) {
    u64 r; asm("mov.b64 %0,{%1,%2};" : "=l"(r) : "f"(lo), "f"(hi)); return r;
}
__device__ __forceinline__ void unpk2(u64 v, float& lo, float& hi) {
    asm("mov.b64 {%0,%1},%2;" : "=f"(lo), "=f"(hi) : "l"(v));
}
__device__ __forceinline__ u64 addp(u64 a, u64 b) {
    u64 r; asm("add.rn.f32x2 %0,%1,%2;" : "=l"(r) : "l"(a), "l"(b)); return r;
}
__device__ __forceinline__ u64 mulp(u64 a, u64 b) {
    u64 r; asm("mul.rn.f32x2 %0,%1,%2;" : "=l"(r) : "l"(a), "l"(b)); return r;
}
__device__ __forceinline__ u64 fmap(u64 a, u64 b, u64 c) {
    u64 r; asm("fma.rn.f32x2 %0,%1,%2,%3;" : "=l"(r) : "l"(a), "l"(b), "l"(c)); return r;
}
__device__ __forceinline__ u64 swapp(u64 v) {
    float lo, hi; unpk2(v, lo, hi); return pk2(hi, lo);
}
// complex mul by twiddle: wc = (c,c), ws = (-s,s);  out = v * (c + i s)
__device__ __forceinline__ u64 cmulw(u64 v, u64 wc, u64 ws) {
    return fmap(swapp(v), ws, mulp(v, wc));
}

// 128-pt DIF FFT, packed. Lane t holds points i = t + 32k, k=0..3.
// Natural-order input; output at position i holds X[rev7(i)].
__device__ __forceinline__ void fft128p(u64 v[4], int t,
                                        const u64* __restrict__ twc,
                                        const u64* __restrict__ tws,
                                        u64 NEG1, u64 P1)
{
    // stage stride 64: pairs (0,2) W^t ; (1,3) W^(t+32)
    {
        u64 d0 = fmap(v[2], NEG1, v[0]); v[0] = addp(v[0], v[2]);
        v[2] = cmulw(d0, twc[t], tws[t]);
        u64 d1 = fmap(v[3], NEG1, v[1]); v[1] = addp(v[1], v[3]);
        v[3] = cmulw(d1, twc[t + 32], tws[t + 32]);
    }
    // stage stride 32: pairs (0,1),(2,3), both W^(2t)
    {
        u64 wc = twc[2 * t], ws = tws[2 * t];
        u64 d0 = fmap(v[1], NEG1, v[0]); v[0] = addp(v[0], v[1]);
        v[1] = cmulw(d0, wc, ws);
        u64 d1 = fmap(v[3], NEG1, v[2]); v[2] = addp(v[2], v[3]);
        v[3] = cmulw(d1, wc, ws);
    }
    // shuffle stages: 4 independent 32-pt FFTs
#pragma unroll
    for (int m = 16; m >= 1; m >>= 1) {
        bool up = (t & m) != 0;
        int idx = up ? (64 / m) * (t & (m - 1)) : 0;
        u64 wc = twc[idx], ws = tws[idx];
        u64 sgn = up ? NEG1 : P1;
#pragma unroll
        for (int k = 0; k < 4; k++) {
            u64 p = __shfl_xor_sync(0xffffffffu, v[k], m);
            u64 s = fmap(v[k], sgn, p);      // up: p - v ; down: p + v
            v[k] = cmulw(s, wc, ws);
        }
    }
}

// Kernel A: per (b,x) plane [y][z]. Z-FFT from global into regs, transpose via
// smem, Y-FFT, write g_fft[b][zs][x][ys] (ys contiguous, coalesced).
__global__ __launch_bounds__(1024, 1)
void k_fft_zy(const float* __restrict__ ref, const float* __restrict__ pred)
{
    extern __shared__ u64 sV[];
    __shared__ u64 twc[64], tws[64];

    int tid = threadIdx.x, t = tid & 31, w = tid >> 5;
    if (tid < 64) {
        float s, c;
        sincosf(-PIF * (float)tid / 64.f, &s, &c);
        twc[tid] = pk2(c, c);
        tws[tid] = pk2(-s, s);
    }
    __syncthreads();
    u64 NEG1 = pk2(-1.f, -1.f), P1 = pk2(1.f, 1.f);

    int b = blockIdx.x >> 7, x = blockIdx.x & 127;
    size_t base = ((size_t)(b * 128 + x)) << 14;

    // Z pass: 32 warps x 4 y-lines
    for (int l = 0; l < 4; l++) {
        int y = w * 4 + l;
        u64 v[4];
#pragma unroll
        for (int k = 0; k < 4; k++) {
            int z = t + 32 * k;
            v[k] = pk2(ref[base + y * 128 + z], pred[base + y * 128 + z]);
        }
        fft128p(v, t, twc, tws, NEG1, P1);
#pragma unroll
        for (int k = 0; k < 4; k++)
            sV[(t + 32 * k) * PAD + y] = v[k];      // row = f(lane): conflict-free
    }
    __syncthreads();

    // Y pass: 32 warps x 4 zs-lines; output straight to global
    for (int l = 0; l < 4; l++) {
        int zs = w * 4 + l;
        u64 v[4];
#pragma unroll
        for (int k = 0; k < 4; k++)
            v[k] = sV[zs * PAD + t + 32 * k];
        fft128p(v, t, twc, tws, NEG1, P1);
        size_t rowbase = ((((size_t)(b * 128 + zs)) << 7 | (unsigned)x) << 7);
#pragma unroll
        for (int k = 0; k < 4; k++)
            g_fft[rowbase + t + 32 * k] = v[k];
    }
}

// Kernel B: per (b,pz) plane [x][ys], fully in-place. X-FFT along columns with
// bit-reversed row write-back (warp-private columns), then store with the
// fy = rev7(ys) column permutation applied. Plane keeps index pz; its
// frequency identity fz = rev7(pz) is resolved in k_reduce.
__global__ __launch_bounds__(1024, 1)
void k_fft_x()
{
    extern __shared__ u64 sV[];
    __shared__ u64 twc[64], tws[64];

    int tid = threadIdx.x, t = tid & 31, w = tid >> 5;
    if (tid < 64) {
        float s, c;
        sincosf(-PIF * (float)tid / 64.f, &s, &c);
        twc[tid] = pk2(c, c);
        tws[tid] = pk2(-s, s);
    }

    int b = blockIdx.x >> 7, pz = blockIdx.x & 127;
    u64* __restrict__ plane = g_fft + (((size_t)(b * 128 + pz)) << 14);
    for (int n = tid; n < 16384; n += 1024) {
        int x = n >> 7, c = n & 127;
        sV[x * PAD + c] = plane[n];
    }
    __syncthreads();   // also covers tw init
    u64 NEG1 = pk2(-1.f, -1.f), P1 = pk2(1.f, 1.f);

    // X-FFT: 32 warps x 4 columns; in-place bit-reversed write to own column
    for (int l = 0; l < 4; l++) {
        int ys = w * 4 + l;
        u64 v[4];
#pragma unroll
        for (int k = 0; k < 4; k++)
            v[k] = sV[(t + 32 * k) * PAD + ys];     // row = f(lane): conflict-free
        fft128p(v, t, twc, tws, NEG1, P1);
        __syncwarp();
#pragma unroll
        for (int k = 0; k < 4; k++)
            sV[rev7(t + 32 * k) * PAD + ys] = v[k];
    }
    __syncthreads();

    // Store back in-place with fy un-reversal: physical col holds fy natural.
    for (int n = tid; n < 16384; n += 1024) {
        int fx = n >> 7, fy = n & 127;
        plane[n] = sV[fx * PAD + rev7(fy)];
    }
}

// Kernel C: Hermitian-pair-halved shell accumulation + fused loss.
// Grid = 8 batches x 65 fz values (fz in [0,64]); weight 2 for fz in 1..63
// (covers skipped partner plane 128-fz; pair contributions are identical),
// weight 1 for self-paired planes fz in {0,64}.
__global__ __launch_bounds__(512)
void k_reduce(float* __restrict__ out)
{
    __shared__ float bins[3 * 65 * 32];   // [comp][shell][lane]
    __shared__ bool sLast;
    __shared__ double ssum[512];
    int tid = threadIdx.x, lane = tid & 31;
    for (int i = tid; i < 3 * 65 * 32; i += 512) bins[i] = 0.f;
    if (tid == 0) sLast = false;
    __syncthreads();

    int bi = blockIdx.x;
    int b = bi / 65, fz = bi % 65;
    int pz  = rev7(fz);
    int fzn = (128 - fz) & 127;
    int pzn = rev7(fzn);
    float wgt = (fz == 0 || fz == 64) ? 1.f : 2.f;
    int szv = fz;                                   // = min(fz, 128-fz) for fz<=64
    const u64* __restrict__ P  = g_fft + (((size_t)(b * 128 + pz )) << 14);
    const u64* __restrict__ Pn = g_fft + (((size_t)(b * 128 + pzn)) << 14);

    for (int n = tid; n < 16384; n += 512) {
        int fx = n >> 7, fy = n & 127;
        int fxn = (128 - fx) & 127, fyn = (128 - fy) & 127;
        float gkx, gky, gmx, gmy;
        unpk2(P[n], gkx, gky);
        unpk2(Pn[(fxn << 7) | fyn], gmx, gmy);
        // A = 2*F1 ; B = 2i*F2 — common x4 scale cancels in FSC
        float ar = gkx + gmx, ai = gky - gmy;
        float br = gkx - gmx, bi2 = gky + gmy;
        float cross = ar * bi2 - ai * br;
        float p1 = ar * ar + ai * ai;
        float p2 = br * br + bi2 * bi2;
        int sx = min(fx, 128 - fx), sy = min(fy, 128 - fy);
        int r2 = sx * sx + sy * sy + szv * szv;
        int s = min(64, (int)sqrtf((float)r2));
        atomicAdd(&bins[(0 * 65 + s) * 32 + lane], cross);
        atomicAdd(&bins[(1 * 65 + s) * 32 + lane], p1);
        atomicAdd(&bins[(2 * 65 + s) * 32 + lane], p2);
    }
    __syncthreads();

    for (int i = tid; i < 3 * 65; i += 512) {
        float acc = 0.f;
#pragma unroll
        for (int j = 0; j < 32; j++) acc += bins[i * 32 + j];
        int comp = i / 65, s = i % 65;
        if (s < 64) atomicAdd(&g_acc[b][s][comp], (double)(acc * wgt));
    }

    // ---- last-block fused loss + state reset for next graph replay ----
    __threadfence();
    __syncthreads();
    if (tid == 0) {
        unsigned done = atomicAdd(&g_ctr, 1u);
        sLast = (done == gridDim.x - 1);
    }
    __syncthreads();
    if (!sLast) return;

    {
        int t = tid;
        int bb = t >> 6, s = t & 63;
        double num = g_acc[bb][s][0];
        double d1  = g_acc[bb][s][1];
        double d2  = g_acc[bb][s][2];
        double fsc = num / (sqrt(d1 * d2) + 1e-8);
        ssum[t] = fsc * fsc;
        __syncthreads();
        for (int off = 256; off > 0; off >>= 1) {
            if (t < off) ssum[t] += ssum[t + off];
            __syncthreads();
        }
        if (t == 0) out[0] = (float)(1.0 - ssum[0] / 512.0);
    }
    __syncthreads();
    // reset accumulators + counter (deterministic per-launch state)
    double* accf = &g_acc[0][0][0];
    for (int i = tid; i < 8 * 65 * 3; i += 512) accf[i] = 0.0;
    if (tid == 0) g_ctr = 0;
}

extern "C" void kernel_launch(void* const* d_in, const int* in_sizes, int n_in,
                              void* d_out, int out_size)
{
    const float* ref  = (const float*)d_in[0];
    const float* pred = (const float*)d_in[1];
    float* out = (float*)d_out;

    cudaFuncSetAttribute(k_fft_zy, cudaFuncAttributeMaxDynamicSharedMemorySize, SMEM_FFT);
    cudaFuncSetAttribute(k_fft_x,  cudaFuncAttributeMaxDynamicSharedMemorySize, SMEM_FFT);

    k_fft_zy<<<1024, 1024, SMEM_FFT>>>(ref, pred);
    k_fft_x<<<1024, 1024, SMEM_FFT>>>();
    k_reduce<<<520, 512>>>(out);
}

// round 6
// speedup vs baseline: 1.2455x; 1.2455x over previous
#include <cuda_runtime.h>
#include <math.h>

// ---------------------------------------------------------------------------
// FSC loss, round 6: warp-per-line 128-pt shuffle FFT (scalar fp32, conflict-
// free smem), kernel A emits natural-frequency layout [b][fz][x][fy], kernel
// B fuses X-FFT + Hermitian pairing + shell reduction + loss (plane-pair
// blocks). Single 134 MB scratch; self-resetting accumulators.
// ---------------------------------------------------------------------------

#define PAD  129      // kernel A plane pad (floats)
#define PADW 33       // kernel B tile pad  (floats)
#define SMEM_A (2 * 128 * PAD * 4)            // 132096 B
#define SMEM_B (4 * 128 * PADW * 4)           // 67584 B (dynamic tiles)
#define PIF 3.14159265358979323846f

static __device__ float2 g_fft[8u * 128u * 128u * 128u];   // 134 MB scratch
static __device__ double g_acc[8][65][3];                  // num, d1, d2
static __device__ unsigned int g_ctr = 0;

__device__ __forceinline__ int rev7(int i) { return (int)(__brev((unsigned)i) >> 25); }

// 128-pt DIF FFT: lane t holds points i = t + 32k, k=0..3.
// Natural-order input; output at position i holds X[rev7(i)].
__device__ __forceinline__ void fft128(float re[4], float im[4], int t,
                                       const float2* __restrict__ tw)
{
    // stage stride 64
    {
        float2 w1 = tw[t], w2 = tw[t + 32];
        float ar, ai;
        ar = re[0] - re[2]; ai = im[0] - im[2];
        re[0] += re[2];     im[0] += im[2];
        re[2] = ar * w1.x - ai * w1.y; im[2] = ar * w1.y + ai * w1.x;
        ar = re[1] - re[3]; ai = im[1] - im[3];
        re[1] += re[3];     im[1] += im[3];
        re[3] = ar * w2.x - ai * w2.y; im[3] = ar * w2.y + ai * w2.x;
    }
    // stage stride 32
    {
        float2 w3 = tw[2 * t];
        float ar, ai;
        ar = re[0] - re[1]; ai = im[0] - im[1];
        re[0] += re[1];     im[0] += im[1];
        re[1] = ar * w3.x - ai * w3.y; im[1] = ar * w3.y + ai * w3.x;
        ar = re[2] - re[3]; ai = im[2] - im[3];
        re[2] += re[3];     im[2] += im[3];
        re[3] = ar * w3.x - ai * w3.y; im[3] = ar * w3.y + ai * w3.x;
    }
    // shuffle stages: 4 independent 32-pt FFTs
#pragma unroll
    for (int m = 16; m >= 1; m >>= 1) {
        bool up = (t & m) != 0;
        int idx = up ? (64 / m) * (t & (m - 1)) : 0;
        float2 wm = tw[idx];
#pragma unroll
        for (int k = 0; k < 4; k++) {
            float pr = __shfl_xor_sync(0xffffffffu, re[k], m);
            float pi = __shfl_xor_sync(0xffffffffu, im[k], m);
            float sr = up ? pr - re[k] : re[k] + pr;
            float si = up ? pi - im[k] : im[k] + pi;
            re[k] = sr * wm.x - si * wm.y;
            im[k] = sr * wm.y + si * wm.x;
        }
    }
}

// Kernel A: per (b,x) plane [y][z]. Z-FFT, transpose via smem, Y-FFT (natural
// slot write-back), then copy-out with fy un-reversal and fz = rev7(zs) plane
// remap -> global natural-frequency layout [b][fz][x][fy].
__global__ __launch_bounds__(1024, 1)
void k_fft_zy(const float* __restrict__ ref, const float* __restrict__ pred)
{
    extern __shared__ float sm[];
    float* sRe = sm;
    float* sIm = sm + 128 * PAD;
    __shared__ float2 tw[64];

    int tid = threadIdx.x, t = tid & 31, w = tid >> 5;
    if (tid < 64) {
        float s, c;
        sincosf(-PIF * (float)tid / 64.f, &s, &c);
        tw[tid] = make_float2(c, s);
    }
    __syncthreads();

    int b = blockIdx.x >> 7, x = blockIdx.x & 127;
    size_t base = ((size_t)(b * 128 + x)) << 14;

    // Z pass: 32 warps x 4 y-lines; transpose into smem (conflict-free)
    for (int l = 0; l < 4; l++) {
        int y = w * 4 + l;
        float re[4], im[4];
#pragma unroll
        for (int k = 0; k < 4; k++) {
            int z = t + 32 * k;
            re[k] = ref[base + y * 128 + z];
            im[k] = pred[base + y * 128 + z];
        }
        fft128(re, im, t, tw);
#pragma unroll
        for (int k = 0; k < 4; k++) {
            int zs = t + 32 * k;
            sRe[zs * PAD + y] = re[k];     // row = f(lane): conflict-free
            sIm[zs * PAD + y] = im[k];
        }
    }
    __syncthreads();

    // Y pass: warp owns zs-row; in-place natural-slot write-back (warp-private)
    for (int l = 0; l < 4; l++) {
        int zs = w * 4 + l;
        float re[4], im[4];
#pragma unroll
        for (int k = 0; k < 4; k++) {
            re[k] = sRe[zs * PAD + t + 32 * k];
            im[k] = sIm[zs * PAD + t + 32 * k];
        }
        fft128(re, im, t, tw);
        __syncwarp();
#pragma unroll
        for (int k = 0; k < 4; k++) {
            sRe[zs * PAD + t + 32 * k] = re[k];   // slot i holds freq rev7(i)
            sIm[zs * PAD + t + 32 * k] = im[k];
        }
    }
    __syncthreads();

    // Copy-out: natural fy (4-way-conflict LDS, one pass), fz = rev7(zs).
    for (int n = tid; n < 16384; n += 1024) {
        int zs = n >> 7, fy = n & 127;
        int c = rev7(fy);
        float2 v = make_float2(sRe[zs * PAD + c], sIm[zs * PAD + c]);
        g_fft[(((size_t)(b * 128 + rev7(zs)) << 7) | (unsigned)x) * 128 + fy] = v;
    }
}

// Kernel B: fused X-FFT + Hermitian-paired shell reduction + loss.
// Block = (b, fz in [0,64], fy-group g in [0,4)). Loads tile P (plane fz,
// cols fy in [32g,32g+32)) and tile Q (plane (128-fz)&127, partner cols),
// X-FFTs all 64 columns, computes cross/p1/p2 per P element with partner
// from Q, bins to shells; weight 2 for fz in 1..63, else 1.
__global__ __launch_bounds__(1024)
void k_fx_reduce(float* __restrict__ out)
{
    extern __shared__ float smB[];
    float* sPre = smB;
    float* sPim = sPre + 128 * PADW;
    float* sQre = sPim + 128 * PADW;
    float* sQim = sQre + 128 * PADW;
    __shared__ float bins[3 * 65 * 32];
    __shared__ float2 tw[64];
    __shared__ double ssum[512];
    __shared__ bool sLast;

    int tid = threadIdx.x, t = tid & 31, w = tid >> 5;
    if (tid < 64) {
        float s, c;
        sincosf(-PIF * (float)tid / 64.f, &s, &c);
        tw[tid] = make_float2(c, s);
    }
    for (int i = tid; i < 3 * 65 * 32; i += 1024) bins[i] = 0.f;
    if (tid == 0) sLast = false;

    int bi = blockIdx.x;
    int b  = bi / 260;
    int r  = bi - b * 260;
    int fz = r >> 2, g = r & 3;
    int fz2 = (128 - fz) & 127;
    float wgt = (fz == 0 || fz == 64) ? 1.f : 2.f;
    size_t basP = ((size_t)(b * 128 + fz )) << 14;
    size_t basQ = ((size_t)(b * 128 + fz2)) << 14;

    // Load tiles: per warp one x-row of 32 cols (coalesced 256B)
    for (int n = tid; n < 4096; n += 1024) {
        int x = n >> 5, j = n & 31;
        int fy  = 32 * g + j;
        int fy2 = (128 - fy) & 127;
        float2 vP = g_fft[basP + ((size_t)x << 7) + fy];
        float2 vQ = g_fft[basQ + ((size_t)x << 7) + fy2];
        sPre[x * PADW + j] = vP.x;  sPim[x * PADW + j] = vP.y;
        sQre[x * PADW + j] = vQ.x;  sQim[x * PADW + j] = vQ.y;
    }
    __syncthreads();

    // X-FFT: 64 columns, 2 per warp; write back at rev7 rows (natural fx order)
    for (int c = 0; c < 2; c++) {
        int idx = w * 2 + c;              // 0..63
        float* Re = (idx & 32) ? sQre : sPre;
        float* Im = (idx & 32) ? sQim : sPim;
        int j = idx & 31;
        float re[4], im[4];
#pragma unroll
        for (int k = 0; k < 4; k++) {
            re[k] = Re[(t + 32 * k) * PADW + j];   // conflict-free
            im[k] = Im[(t + 32 * k) * PADW + j];
        }
        fft128(re, im, t, tw);
        __syncwarp();
#pragma unroll
        for (int k = 0; k < 4; k++) {
            int fx = rev7(t + 32 * k);
            Re[fx * PADW + j] = re[k];
            Im[fx * PADW + j] = im[k];
        }
    }
    __syncthreads();

    // Product + shell binning: element (fx, fy, fz) of P, partner from Q.
    for (int n = tid; n < 4096; n += 1024) {
        int fx = n >> 5, j = n & 31;
        int fx2 = (128 - fx) & 127;
        float gkx = sPre[fx * PADW + j],  gky = sPim[fx * PADW + j];
        float gmx = sQre[fx2 * PADW + j], gmy = sQim[fx2 * PADW + j];
        // A = 2*F1 ; B = 2i*F2 — common x4 scale cancels in FSC
        float ar = gkx + gmx, ai = gky - gmy;
        float br = gkx - gmx, bi2 = gky + gmy;
        float cross = ar * bi2 - ai * br;
        float p1 = ar * ar + ai * ai;
        float p2 = br * br + bi2 * bi2;
        int fy = 32 * g + j;
        int sx = min(fx, 128 - fx), sy = min(fy, 128 - fy);
        int r2 = sx * sx + sy * sy + fz * fz;
        int s = min(64, (int)sqrtf((float)r2));
        atomicAdd(&bins[(0 * 65 + s) * 32 + t], cross);
        atomicAdd(&bins[(1 * 65 + s) * 32 + t], p1);
        atomicAdd(&bins[(2 * 65 + s) * 32 + t], p2);
    }
    __syncthreads();

    for (int i = tid; i < 3 * 65; i += 1024) {
        float acc = 0.f;
#pragma unroll
        for (int j = 0; j < 32; j++) acc += bins[i * 32 + j];
        int comp = i / 65, s = i - comp * 65;
        if (s < 64) atomicAdd(&g_acc[b][s][comp], (double)(acc * wgt));
    }

    // ---- last-block fused loss + state reset ----
    __threadfence();
    __syncthreads();
    if (tid == 0) {
        unsigned done = atomicAdd(&g_ctr, 1u);
        sLast = (done == gridDim.x - 1);
    }
    __syncthreads();
    if (!sLast) return;

    if (tid < 512) {
        int bb = tid >> 6, s = tid & 63;
        double num = g_acc[bb][s][0];
        double d1  = g_acc[bb][s][1];
        double d2  = g_acc[bb][s][2];
        double fsc = num / (sqrt(d1 * d2) + 1e-8);
        ssum[tid] = fsc * fsc;
    }
    __syncthreads();
    for (int off = 256; off > 0; off >>= 1) {
        if (tid < off) ssum[tid] += ssum[tid + off];
        __syncthreads();
    }
    if (tid == 0) out[0] = (float)(1.0 - ssum[0] / 512.0);
    __syncthreads();
    double* accf = &g_acc[0][0][0];
    for (int i = tid; i < 8 * 65 * 3; i += 1024) accf[i] = 0.0;
    if (tid == 0) g_ctr = 0;
}

extern "C" void kernel_launch(void* const* d_in, const int* in_sizes, int n_in,
                              void* d_out, int out_size)
{
    const float* ref  = (const float*)d_in[0];
    const float* pred = (const float*)d_in[1];
    float* out = (float*)d_out;

    cudaFuncSetAttribute(k_fft_zy,    cudaFuncAttributeMaxDynamicSharedMemorySize, SMEM_A);
    cudaFuncSetAttribute(k_fx_reduce, cudaFuncAttributeMaxDynamicSharedMemorySize, SMEM_B);

    k_fft_zy<<<1024, 1024, SMEM_A>>>(ref, pred);
    k_fx_reduce<<<2080, 1024, SMEM_B>>>(out);
}